// round 2
// baseline (speedup 1.0000x reference)
#include <cuda_runtime.h>
#include <cstdint>
#include <math.h>

// POLY2: out_b = sigmoid( sum_{i<j} w_ij * x_bi * x_bj )
//   S = X @ W (W strictly upper-tri, [k][n], k<n), y_b = sum_n S[b,n]*x[b,n]
// compute_103 target: no tcgen05. Use legacy mma.sync tf32 + cp.async pipeline.

#define F        1024
#define BATCHN   16384
#define M_TILE   128
#define N_TILE   128
#define K_CHUNK  32
#define CHUNKS   (F / K_CHUNK)     // 32
#define NTHREADS 256

// smem layout (floats, padded strides for conflict-free LDS)
#define STRIDE_A 36                 // 128B data + pad, 144B row (16B aligned)
#define STRIDE_B 136                // 512B data + pad, 544B row (16B aligned)
#define A_BYTES  (128 * STRIDE_A * 4)   // 18432
#define B_BYTES  (K_CHUNK * STRIDE_B * 4) // 17408
#define A_OFF0   0
#define A_OFF1   A_BYTES
#define B_OFF0   (2 * A_BYTES)
#define B_OFF1   (2 * A_BYTES + B_BYTES)
#define PART_OFF (2 * A_BYTES + 2 * B_BYTES)   // 71680
#define SMEM_TOTAL (PART_OFF + 128 * 4)        // 72192

__device__ float d_W2[F * F];        // W2[k][n] = w_{kn} for k<n else 0 (tf32-rna bits)
__device__ float d_scratch[BATCHN];  // partial z accumulators

// ---------------- helpers ----------------
__device__ __forceinline__ uint32_t smem_u32(const void* p) {
    uint32_t a;
    asm("{ .reg .u64 t; cvta.to.shared.u64 t, %1; cvt.u32.u64 %0, t; }" : "=r"(a) : "l"(p));
    return a;
}
__device__ __forceinline__ void cp16(uint32_t dst, const void* src) {
    asm volatile("cp.async.cg.shared.global [%0], [%1], 16;" :: "r"(dst), "l"(src) : "memory");
}
__device__ __forceinline__ void cp_commit() { asm volatile("cp.async.commit_group;" ::: "memory"); }
__device__ __forceinline__ void cp_wait1()  { asm volatile("cp.async.wait_group 1;"  ::: "memory"); }

__device__ __forceinline__ uint32_t f2tf32(float f) {
    uint32_t r;
    asm("cvt.rna.tf32.f32 %0, %1;" : "=r"(r) : "f"(f));
    return r;
}
__device__ __forceinline__ void mma_tf32(float* c, const uint32_t* a, const uint32_t* b) {
    asm volatile(
        "mma.sync.aligned.m16n8k8.row.col.f32.tf32.tf32.f32 "
        "{%0,%1,%2,%3}, {%4,%5,%6,%7}, {%8,%9}, {%0,%1,%2,%3};"
        : "+f"(c[0]), "+f"(c[1]), "+f"(c[2]), "+f"(c[3])
        : "r"(a[0]), "r"(a[1]), "r"(a[2]), "r"(a[3]), "r"(b[0]), "r"(b[1]));
}

// ---------------- W scatter: w (triu row-major order) -> W2[k][n], tf32-rna ----------------
__global__ void build_w2_kernel(const float* __restrict__ w) {
    int idx = blockIdx.x * 256 + threadIdx.x;  // over F*F
    int k = idx >> 10;
    int n = idx & (F - 1);
    uint32_t v = 0u;
    if (k < n) {
        // pair (i=k, j=n): index = i*(F-1) - i*(i-1)/2 + (j-i-1)
        int pi = k * (F - 1) - (k * (k - 1)) / 2 + (n - k - 1);
        v = f2tf32(w[pi]);
    }
    reinterpret_cast<uint32_t*>(d_W2)[idx] = v;
}

__global__ void zero_scratch_kernel() {
    d_scratch[blockIdx.x * 256 + threadIdx.x] = 0.0f;
}

__global__ void sigmoid_kernel(float* __restrict__ out) {
    int i = blockIdx.x * 256 + threadIdx.x;
    out[i] = 1.0f / (1.0f + __expf(-d_scratch[i]));
}

// ---------------- stage loader ----------------
__device__ __forceinline__ void issue_stage(uint32_t sb, int buf, int k0,
                                            const float* __restrict__ x,
                                            int m0, int n0, int tid) {
    uint32_t abase = sb + (buf ? A_OFF1 : A_OFF0);
    uint32_t bbase = sb + (buf ? B_OFF1 : B_OFF0);
    // A: X[m0+m][k0 + c*4 ..], 128 rows x 8 16B-chunks = 1024
    #pragma unroll
    for (int j = 0; j < 4; ++j) {
        int q = j * NTHREADS + tid;
        int m = q >> 3, c = q & 7;
        cp16(abase + (uint32_t)(m * (STRIDE_A * 4) + c * 16),
             x + (size_t)(m0 + m) * F + k0 + c * 4);
    }
    // B: W2[k0+k][n0 + c*4 ..], 32 rows x 32 16B-chunks = 1024
    #pragma unroll
    for (int j = 0; j < 4; ++j) {
        int q = j * NTHREADS + tid;
        int k = q >> 5, c = q & 31;
        cp16(bbase + (uint32_t)(k * (STRIDE_B * 4) + c * 16),
             d_W2 + (size_t)(k0 + k) * F + n0 + c * 4);
    }
}

// ---------------- main GEMM + fused rowdot ----------------
extern __shared__ char smem_buf[];

__global__ void __launch_bounds__(NTHREADS, 2)
poly2_gemm_kernel(const float* __restrict__ x) {
    uint32_t sb = smem_u32(smem_buf);
    float* As0 = reinterpret_cast<float*>(smem_buf + A_OFF0);
    float* As1 = reinterpret_cast<float*>(smem_buf + A_OFF1);
    float* Bs0 = reinterpret_cast<float*>(smem_buf + B_OFF0);
    float* Bs1 = reinterpret_cast<float*>(smem_buf + B_OFF1);
    float* part = reinterpret_cast<float*>(smem_buf + PART_OFF);

    int tid = threadIdx.x;
    int lane = tid & 31;
    int wid = tid >> 5;
    int warpM = wid & 3;         // 4 warps along M
    int warpN = wid >> 2;        // 2 warps along N
    int m0 = blockIdx.x * M_TILE;
    int n0 = blockIdx.y * N_TILE;

    float acc[2][8][4];          // [mtile(16)][ntile(8)][4]
    #pragma unroll
    for (int mt = 0; mt < 2; ++mt)
        #pragma unroll
        for (int nt = 0; nt < 8; ++nt)
            #pragma unroll
            for (int r = 0; r < 4; ++r) acc[mt][nt][r] = 0.0f;

    // prologue
    issue_stage(sb, 0, 0,       x, m0, n0, tid); cp_commit();
    issue_stage(sb, 1, K_CHUNK, x, m0, n0, tid); cp_commit();

    int a_row = warpM * 32 + (lane >> 2);          // base A row in tile
    int b_col = warpN * 64 + (lane >> 2);          // base B col in tile
    int kq    = lane & 3;

    for (int ck = 0; ck < CHUNKS; ++ck) {
        cp_wait1();
        __syncthreads();
        const float* As = (ck & 1) ? As1 : As0;
        const float* Bs = (ck & 1) ? Bs1 : Bs0;

        #pragma unroll
        for (int ks = 0; ks < 4; ++ks) {
            int kk = ks * 8 + kq;
            uint32_t a[2][4];
            #pragma unroll
            for (int mt = 0; mt < 2; ++mt) {
                int r = a_row + mt * 16;
                a[mt][0] = f2tf32(As[r * STRIDE_A + kk]);
                a[mt][1] = f2tf32(As[(r + 8) * STRIDE_A + kk]);
                a[mt][2] = f2tf32(As[r * STRIDE_A + kk + 4]);
                a[mt][3] = f2tf32(As[(r + 8) * STRIDE_A + kk + 4]);
            }
            const uint32_t* Bu = reinterpret_cast<const uint32_t*>(Bs);
            #pragma unroll
            for (int nt = 0; nt < 8; ++nt) {
                uint32_t b[2];
                int n = b_col + nt * 8;
                b[0] = Bu[kk * STRIDE_B + n];
                b[1] = Bu[(kk + 4) * STRIDE_B + n];
                mma_tf32(acc[0][nt], a[0], b);
                mma_tf32(acc[1][nt], a[1], b);
            }
        }
        __syncthreads();
        if (ck + 2 < CHUNKS)
            issue_stage(sb, ck & 1, (ck + 2) * K_CHUNK, x, m0, n0, tid);
        cp_commit();
    }

    // ---------------- epilogue: rowdot S * x ----------------
    if (tid < 128) part[tid] = 0.0f;
    __syncthreads();

    #pragma unroll
    for (int mt = 0; mt < 2; ++mt) {
        float ps0 = 0.0f, ps1 = 0.0f;   // rows: base, base+8
        #pragma unroll
        for (int nt = 0; nt < 8; ++nt) {
            int col = n0 + warpN * 64 + nt * 8 + (lane & 3) * 2;
            int rowg = m0 + warpM * 32 + mt * 16 + (lane >> 2);
            float2 x0 = *reinterpret_cast<const float2*>(x + (size_t)rowg * F + col);
            float2 x1 = *reinterpret_cast<const float2*>(x + (size_t)(rowg + 8) * F + col);
            ps0 += acc[mt][nt][0] * x0.x + acc[mt][nt][1] * x0.y;
            ps1 += acc[mt][nt][2] * x1.x + acc[mt][nt][3] * x1.y;
        }
        // reduce over lane&3 group (4 lanes hold disjoint cols of same row)
        ps0 += __shfl_xor_sync(0xffffffffu, ps0, 1);
        ps0 += __shfl_xor_sync(0xffffffffu, ps0, 2);
        ps1 += __shfl_xor_sync(0xffffffffu, ps1, 1);
        ps1 += __shfl_xor_sync(0xffffffffu, ps1, 2);
        if ((lane & 3) == 0) {
            int rl = warpM * 32 + mt * 16 + (lane >> 2);
            atomicAdd(&part[rl], ps0);
            atomicAdd(&part[rl + 8], ps1);
        }
    }
    __syncthreads();
    if (tid < 128) atomicAdd(&d_scratch[m0 + tid], part[tid]);
}

// ---------------- launch ----------------
extern "C" void kernel_launch(void* const* d_in, const int* in_sizes, int n_in,
                              void* d_out, int out_size) {
    const float* x = (const float*)d_in[0];     // [16384, 1024] fp32
    const float* w = (const float*)d_in[1];     // [523776] fp32
    float* out = (float*)d_out;                 // [16384] fp32

    build_w2_kernel<<<(F * F) / 256, 256>>>(w);
    zero_scratch_kernel<<<BATCHN / 256, 256>>>();

    cudaFuncSetAttribute(poly2_gemm_kernel,
                         cudaFuncAttributeMaxDynamicSharedMemorySize, SMEM_TOTAL);
    dim3 grid(BATCHN / M_TILE, F / N_TILE);     // 128 x 8
    poly2_gemm_kernel<<<grid, NTHREADS, SMEM_TOTAL>>>(x);

    sigmoid_kernel<<<BATCHN / 256, 256>>>(out);
}

// round 4
// speedup vs baseline: 2.0874x; 2.0874x over previous
#include <cuda_runtime.h>
#include <cuda_fp16.h>
#include <cstdint>
#include <math.h>

// POLY2: out_b = sigmoid( sum_{i<j} w_ij * x_bi * x_bj )
//   S = X @ W  (W strictly upper-tri), y_b = sum_n S[b,n]*x[b,n]
// fp16 mma.sync.m16n8k16 (same mantissa as tf32, 2x rate), cp.async pipeline,
// triangular K-skip: N-block j only needs k < 128*(j+1)  (56% of full GEMM).

#define F        1024
#define BATCHN   16384
#define M_TILE   128
#define N_TILE   128
#define K_CHUNK  64
#define NTHREADS 256

// smem (bytes)
#define STRIDE_A_W 36        // A row stride in 4B words (64 halves = 128B data + 16B pad)
#define STRIDE_B_W 132       // B pair-row stride in 4B words (128 half2 = 512B data + 16B pad)
#define A_BYTES    (128 * STRIDE_A_W * 4)   // 18432
#define B_BYTES    (32 * STRIDE_B_W * 4)    // 16896
#define A_OFF0     0
#define A_OFF1     A_BYTES
#define B_OFF0     (2 * A_BYTES)
#define B_OFF1     (2 * A_BYTES + B_BYTES)
#define PART_OFF   (2 * A_BYTES + 2 * B_BYTES)   // 70656
#define SMEM_TOTAL (PART_OFF + 128 * 4)          // 71168

__device__ __half  d_Xh[BATCHN * F];     // X in fp16 (row-major)
__device__ __half2 d_W2h[F * F / 2];     // W k-pair-interleaved: [k/2][n] = (w_{k,n}, w_{k+1,n})
__device__ float   d_scratch[BATCHN];    // partial z accumulators

// ---------------- helpers ----------------
__device__ __forceinline__ uint32_t smem_u32(const void* p) {
    uint32_t a;
    asm("{ .reg .u64 t; cvta.to.shared.u64 t, %1; cvt.u32.u64 %0, t; }" : "=r"(a) : "l"(p));
    return a;
}
__device__ __forceinline__ void cp16(uint32_t dst, const void* src) {
    asm volatile("cp.async.cg.shared.global [%0], [%1], 16;" :: "r"(dst), "l"(src) : "memory");
}
__device__ __forceinline__ void cp_commit() { asm volatile("cp.async.commit_group;" ::: "memory"); }
__device__ __forceinline__ void cp_wait1()  { asm volatile("cp.async.wait_group 1;"  ::: "memory"); }

__device__ __forceinline__ void mma16816(float* c, const uint32_t* a, uint32_t b0, uint32_t b1) {
    asm volatile(
        "mma.sync.aligned.m16n8k16.row.col.f32.f16.f16.f32 "
        "{%0,%1,%2,%3}, {%4,%5,%6,%7}, {%8,%9}, {%0,%1,%2,%3};"
        : "+f"(c[0]), "+f"(c[1]), "+f"(c[2]), "+f"(c[3])
        : "r"(a[0]), "r"(a[1]), "r"(a[2]), "r"(a[3]), "r"(b0), "r"(b1));
}

// ---------------- pre-kernels ----------------
__global__ void convert_x_kernel(const float* __restrict__ x) {
    int i = (blockIdx.x * 256 + threadIdx.x) * 8;
    float4 v0 = *reinterpret_cast<const float4*>(x + i);
    float4 v1 = *reinterpret_cast<const float4*>(x + i + 4);
    __half2 h[4];
    h[0] = __floats2half2_rn(v0.x, v0.y);
    h[1] = __floats2half2_rn(v0.z, v0.w);
    h[2] = __floats2half2_rn(v1.x, v1.y);
    h[3] = __floats2half2_rn(v1.z, v1.w);
    *reinterpret_cast<uint4*>(d_Xh + i) = *reinterpret_cast<uint4*>(h);
}

// triu pair index for (i=k, j=n), i<j: pi = k*(F-1) - k*(k-1)/2 + (n-k-1)
__device__ __forceinline__ float w_at(const float* __restrict__ w, int k, int n) {
    if (k >= n) return 0.0f;
    int pi = k * (F - 1) - (k * (k - 1)) / 2 + (n - k - 1);
    return w[pi];
}
__global__ void build_w2h_kernel(const float* __restrict__ w) {
    int idx = blockIdx.x * 256 + threadIdx.x;   // over F/2 * F
    int k2 = idx >> 10;
    int n  = idx & (F - 1);
    float f0 = w_at(w, 2 * k2, n);
    float f1 = w_at(w, 2 * k2 + 1, n);
    d_W2h[idx] = __floats2half2_rn(f0, f1);
}

__global__ void zero_scratch_kernel() {
    d_scratch[blockIdx.x * 256 + threadIdx.x] = 0.0f;
}
__global__ void sigmoid_kernel(float* __restrict__ out) {
    int i = blockIdx.x * 256 + threadIdx.x;
    out[i] = 1.0f / (1.0f + __expf(-d_scratch[i]));
}

// ---------------- stage loader ----------------
__device__ __forceinline__ void issue_stage(uint32_t sb, int buf, int k0,
                                            int m0, int n0, int tid) {
    uint32_t abase = sb + (buf ? A_OFF1 : A_OFF0);
    uint32_t bbase = sb + (buf ? B_OFF1 : B_OFF0);
    // A: 128 rows x 8 16B-chunks (64 halves = 128B/row); src stride 8 halves/chunk
    #pragma unroll
    for (int j = 0; j < 4; ++j) {
        int q = j * NTHREADS + tid;
        int m = q >> 3, c = q & 7;
        cp16(abase + (uint32_t)(m * (STRIDE_A_W * 4) + c * 16),
             d_Xh + (size_t)(m0 + m) * F + k0 + c * 8);
    }
    // B: 32 pair-rows x 32 16B-chunks (128 half2 = 512B/row); src 4 half2/chunk
    int k20 = k0 >> 1;
    #pragma unroll
    for (int j = 0; j < 4; ++j) {
        int q = j * NTHREADS + tid;
        int p = q >> 5, c = q & 31;
        cp16(bbase + (uint32_t)(p * (STRIDE_B_W * 4) + c * 16),
             d_W2h + (size_t)(k20 + p) * F + n0 + c * 4);
    }
}

// ---------------- main GEMM + fused rowdot ----------------
extern __shared__ char smem_buf[];

__global__ void __launch_bounds__(NTHREADS, 2)
poly2_gemm_kernel(const float* __restrict__ x) {
    uint32_t sb = smem_u32(smem_buf);
    float* part = reinterpret_cast<float*>(smem_buf + PART_OFF);

    int tid  = threadIdx.x;
    int lane = tid & 31;
    int wid  = tid >> 5;
    int warpM = wid & 3;        // 4 warps along M
    int warpN = wid >> 2;       // 2 warps along N
    int m0 = blockIdx.x * M_TILE;
    int n0 = blockIdx.y * N_TILE;

    // triangular skip: W2[k][n] == 0 for k >= n, so only k < n0 + N_TILE matters
    int nchunks = (n0 + N_TILE) / K_CHUNK;    // 2..16

    float acc[2][8][4];
    #pragma unroll
    for (int mt = 0; mt < 2; ++mt)
        #pragma unroll
        for (int nt = 0; nt < 8; ++nt)
            #pragma unroll
            for (int r = 0; r < 4; ++r) acc[mt][nt][r] = 0.0f;

    issue_stage(sb, 0, 0,       m0, n0, tid); cp_commit();
    issue_stage(sb, 1, K_CHUNK, m0, n0, tid); cp_commit();

    int a_row = warpM * 32 + (lane >> 2);
    int b_col = warpN * 64 + (lane >> 2);

    for (int ck = 0; ck < nchunks; ++ck) {
        cp_wait1();
        __syncthreads();
        const uint32_t* As = reinterpret_cast<const uint32_t*>(smem_buf + ((ck & 1) ? A_OFF1 : A_OFF0));
        const uint32_t* Bs = reinterpret_cast<const uint32_t*>(smem_buf + ((ck & 1) ? B_OFF1 : B_OFF0));

        #pragma unroll
        for (int ks = 0; ks < 4; ++ks) {
            int aw = ks * 8 + (lane & 3);          // word index: halves k = ks*16 + 2*(lane&3)
            uint32_t a[2][4];
            #pragma unroll
            for (int mt = 0; mt < 2; ++mt) {
                int r = a_row + mt * 16;
                a[mt][0] = As[r * STRIDE_A_W + aw];
                a[mt][1] = As[(r + 8) * STRIDE_A_W + aw];
                a[mt][2] = As[r * STRIDE_A_W + aw + 4];
                a[mt][3] = As[(r + 8) * STRIDE_A_W + aw + 4];
            }
            int p0 = ks * 8 + (lane & 3);          // pair-row: k = ks*16 + 2*(lane&3)
            #pragma unroll
            for (int nt = 0; nt < 8; ++nt) {
                int n = b_col + nt * 8;
                uint32_t b0 = Bs[p0 * STRIDE_B_W + n];
                uint32_t b1 = Bs[(p0 + 4) * STRIDE_B_W + n];
                mma16816(acc[0][nt], a[0], b0, b1);
                mma16816(acc[1][nt], a[1], b0, b1);
            }
        }
        __syncthreads();
        if (ck + 2 < nchunks)
            issue_stage(sb, ck & 1, (ck + 2) * K_CHUNK, m0, n0, tid);
        cp_commit();
    }

    // ---------------- epilogue: rowdot S * x ----------------
    if (tid < 128) part[tid] = 0.0f;
    __syncthreads();

    #pragma unroll
    for (int mt = 0; mt < 2; ++mt) {
        float ps0 = 0.0f, ps1 = 0.0f;
        #pragma unroll
        for (int nt = 0; nt < 8; ++nt) {
            int col  = n0 + warpN * 64 + nt * 8 + (lane & 3) * 2;
            int rowg = m0 + warpM * 32 + mt * 16 + (lane >> 2);
            float2 x0 = *reinterpret_cast<const float2*>(x + (size_t)rowg * F + col);
            float2 x1 = *reinterpret_cast<const float2*>(x + (size_t)(rowg + 8) * F + col);
            ps0 += acc[mt][nt][0] * x0.x + acc[mt][nt][1] * x0.y;
            ps1 += acc[mt][nt][2] * x1.x + acc[mt][nt][3] * x1.y;
        }
        ps0 += __shfl_xor_sync(0xffffffffu, ps0, 1);
        ps0 += __shfl_xor_sync(0xffffffffu, ps0, 2);
        ps1 += __shfl_xor_sync(0xffffffffu, ps1, 1);
        ps1 += __shfl_xor_sync(0xffffffffu, ps1, 2);
        if ((lane & 3) == 0) {
            int rl = warpM * 32 + mt * 16 + (lane >> 2);
            atomicAdd(&part[rl], ps0);
            atomicAdd(&part[rl + 8], ps1);
        }
    }
    __syncthreads();
    if (tid < 128) atomicAdd(&d_scratch[m0 + tid], part[tid]);
}

// ---------------- launch ----------------
extern "C" void kernel_launch(void* const* d_in, const int* in_sizes, int n_in,
                              void* d_out, int out_size) {
    const float* x = (const float*)d_in[0];     // [16384, 1024] fp32
    const float* w = (const float*)d_in[1];     // [523776] fp32
    float* out = (float*)d_out;                 // [16384] fp32

    convert_x_kernel<<<(BATCHN * F) / (256 * 8), 256>>>(x);
    build_w2h_kernel<<<(F * F / 2) / 256, 256>>>(w);
    zero_scratch_kernel<<<BATCHN / 256, 256>>>();

    cudaFuncSetAttribute(poly2_gemm_kernel,
                         cudaFuncAttributeMaxDynamicSharedMemorySize, SMEM_TOTAL);
    dim3 grid(BATCHN / M_TILE, F / N_TILE);     // 128 x 8
    poly2_gemm_kernel<<<grid, NTHREADS, SMEM_TOTAL>>>(x);

    sigmoid_kernel<<<BATCHN / 256, 256>>>(out);
}

// round 6
// speedup vs baseline: 2.3391x; 1.1206x over previous
#include <cuda_runtime.h>
#include <cuda_fp16.h>
#include <cstdint>
#include <math.h>

// POLY2: out_b = sigmoid( sum_{i<j} w_ij * x_bi * x_bj )
//   S = X @ W (W strictly upper-tri), y_b = sum_n S[b,n]*x[b,n]
// fp16 mma.sync.m16n8k16, ldmatrix.x4 fragment loads, cp.async double buffer,
// triangular K-skip (56% of full GEMM), heavy-tile-first scheduling.

#define F        1024
#define BATCHN   16384
#define M_TILE   128
#define N_TILE   128
#define K_CHUNK  64
#define NTHREADS 256

// smem: A and B tiles both 128 rows x 64 halves, padded row stride 144B
#define ROW_B      144
#define TILE_BYTES (128 * ROW_B)            // 18432
#define A_OFF0     0
#define A_OFF1     TILE_BYTES
#define B_OFF0     (2 * TILE_BYTES)
#define B_OFF1     (3 * TILE_BYTES)
#define PART_OFF   (4 * TILE_BYTES)          // 73728
#define SMEM_TOTAL (PART_OFF + 128 * 4)      // 74240

__device__ __half d_Xh[BATCHN * F];      // X fp16 row-major
__device__ __half d_Wth[F * F];          // Wt[n][k] = w_{k,n} (k<n else 0), k contiguous
__device__ float  d_scratch[BATCHN];

// ---------------- helpers ----------------
__device__ __forceinline__ uint32_t smem_u32(const void* p) {
    uint32_t a;
    asm("{ .reg .u64 t; cvta.to.shared.u64 t, %1; cvt.u32.u64 %0, t; }" : "=r"(a) : "l"(p));
    return a;
}
__device__ __forceinline__ void cp16(uint32_t dst, const void* src) {
    asm volatile("cp.async.cg.shared.global [%0], [%1], 16;" :: "r"(dst), "l"(src) : "memory");
}
__device__ __forceinline__ void cp_commit() { asm volatile("cp.async.commit_group;" ::: "memory"); }
__device__ __forceinline__ void cp_wait1()  { asm volatile("cp.async.wait_group 1;"  ::: "memory"); }

__device__ __forceinline__ void ldsm4(uint32_t* r, uint32_t addr) {
    asm volatile("ldmatrix.sync.aligned.m8n8.x4.shared.b16 {%0,%1,%2,%3}, [%4];"
        : "=r"(r[0]), "=r"(r[1]), "=r"(r[2]), "=r"(r[3]) : "r"(addr));
}
__device__ __forceinline__ void mma16816(float* c, const uint32_t* a, uint32_t b0, uint32_t b1) {
    asm volatile(
        "mma.sync.aligned.m16n8k16.row.col.f32.f16.f16.f32 "
        "{%0,%1,%2,%3}, {%4,%5,%6,%7}, {%8,%9}, {%0,%1,%2,%3};"
        : "+f"(c[0]), "+f"(c[1]), "+f"(c[2]), "+f"(c[3])
        : "r"(a[0]), "r"(a[1]), "r"(a[2]), "r"(a[3]), "r"(b0), "r"(b1));
}

// ---------------- pre-kernels ----------------
__global__ void convert_x_kernel(const float* __restrict__ x) {
    int i = (blockIdx.x * 256 + threadIdx.x) * 8;
    float4 v0 = *reinterpret_cast<const float4*>(x + i);
    float4 v1 = *reinterpret_cast<const float4*>(x + i + 4);
    __half2 h[4];
    h[0] = __floats2half2_rn(v0.x, v0.y);
    h[1] = __floats2half2_rn(v0.z, v0.w);
    h[2] = __floats2half2_rn(v1.x, v1.y);
    h[3] = __floats2half2_rn(v1.z, v1.w);
    *reinterpret_cast<uint4*>(d_Xh + i) = *reinterpret_cast<uint4*>(h);
}

// triu pair index for (i=k, j=n), i<j
__device__ __forceinline__ float w_at(const float* __restrict__ w, int k, int n) {
    if (k >= n) return 0.0f;
    int pi = k * (F - 1) - (k * (k - 1)) / 2 + (n - k - 1);
    return w[pi];
}
__global__ void build_wt_kernel(const float* __restrict__ w) {
    int idx = blockIdx.x * 256 + threadIdx.x;   // over F*F/2 half2 slots
    int n  = idx >> 9;
    int k2 = idx & 511;
    float f0 = w_at(w, 2 * k2,     n);
    float f1 = w_at(w, 2 * k2 + 1, n);
    reinterpret_cast<__half2*>(d_Wth)[idx] = __floats2half2_rn(f0, f1);
}
__global__ void zero_scratch_kernel() {
    d_scratch[blockIdx.x * 256 + threadIdx.x] = 0.0f;
}
__global__ void sigmoid_kernel(float* __restrict__ out) {
    int i = blockIdx.x * 256 + threadIdx.x;
    out[i] = 1.0f / (1.0f + __expf(-d_scratch[i]));
}

// ---------------- stage loader: A=Xh[m0..][k0..k0+64), B=Wt[n0..][k0..k0+64) ----------------
__device__ __forceinline__ void issue_stage(uint32_t sb, int buf, int k0,
                                            int m0, int n0, int tid) {
    uint32_t abase = sb + (buf ? A_OFF1 : A_OFF0);
    uint32_t bbase = sb + (buf ? B_OFF1 : B_OFF0);
    #pragma unroll
    for (int j = 0; j < 4; ++j) {                    // A: 128 rows x 8 chunks
        int q = j * NTHREADS + tid;
        int m = q >> 3, c = q & 7;
        cp16(abase + (uint32_t)(m * ROW_B + c * 16),
             d_Xh + (size_t)(m0 + m) * F + k0 + c * 8);
    }
    #pragma unroll
    for (int j = 0; j < 4; ++j) {                    // B: 128 rows x 8 chunks
        int q = j * NTHREADS + tid;
        int n = q >> 3, c = q & 7;
        cp16(bbase + (uint32_t)(n * ROW_B + c * 16),
             d_Wth + (size_t)(n0 + n) * F + k0 + c * 8);
    }
}

// ---------------- main GEMM + fused rowdot ----------------
extern __shared__ char smem_buf[];

__global__ void __launch_bounds__(NTHREADS, 2)
poly2_gemm_kernel(const float* __restrict__ x) {
    uint32_t sb = smem_u32(smem_buf);
    float* part = reinterpret_cast<float*>(smem_buf + PART_OFF);

    int tid  = threadIdx.x;
    int lane = tid & 31;
    int wid  = tid >> 5;
    int warpM = wid & 3;                 // 4 warps along M (tile 32)
    int warpN = wid >> 2;                // 2 warps along N (tile 64)
    int m0 = blockIdx.x * M_TILE;
    int by = (int)gridDim.y - 1 - (int)blockIdx.y;   // heavy tiles first
    int n0 = by * N_TILE;

    int nchunks = (n0 + N_TILE) / K_CHUNK;           // triangular skip: 2..16

    float acc[2][8][4];
    #pragma unroll
    for (int mt = 0; mt < 2; ++mt)
        #pragma unroll
        for (int nt = 0; nt < 8; ++nt)
            #pragma unroll
            for (int r = 0; r < 4; ++r) acc[mt][nt][r] = 0.0f;

    issue_stage(sb, 0, 0,       m0, n0, tid); cp_commit();
    issue_stage(sb, 1, K_CHUNK, m0, n0, tid); cp_commit();

    // per-lane ldmatrix address offsets (row-major tiles, 144B row stride)
    // lanes 0-15 -> rows +0..15 (k-lo half), lanes 16-31 -> same rows, k-hi (+16B)
    uint32_t lrow = (uint32_t)(lane & 15);
    uint32_t khalf = (uint32_t)((lane >> 4) * 16);   // bytes
    uint32_t aoff = (uint32_t)(warpM * 32) * ROW_B + lrow * ROW_B + khalf;
    uint32_t boff = (uint32_t)(warpN * 64) * ROW_B + lrow * ROW_B + khalf;

    for (int ck = 0; ck < nchunks; ++ck) {
        cp_wait1();
        __syncthreads();
        uint32_t abase = sb + ((ck & 1) ? A_OFF1 : A_OFF0);
        uint32_t bbase = sb + ((ck & 1) ? B_OFF1 : B_OFF0);
        uint32_t aAddr = abase + aoff;
        uint32_t bAddr = bbase + boff;

        #pragma unroll
        for (int ks = 0; ks < 4; ++ks) {
            uint32_t a[2][4];
            ldsm4(a[0], aAddr + ks * 32);
            ldsm4(a[1], aAddr + 16 * ROW_B + ks * 32);
            #pragma unroll
            for (int g = 0; g < 4; ++g) {
                uint32_t b[4];
                ldsm4(b, bAddr + (uint32_t)(g * 16) * ROW_B + ks * 32);
                // b[0]=b0(nt=2g), b[1]=b0(nt=2g+1), b[2]=b1(nt=2g), b[3]=b1(nt=2g+1)
                mma16816(acc[0][2 * g],     a[0], b[0], b[2]);
                mma16816(acc[0][2 * g + 1], a[0], b[1], b[3]);
                mma16816(acc[1][2 * g],     a[1], b[0], b[2]);
                mma16816(acc[1][2 * g + 1], a[1], b[1], b[3]);
            }
        }
        __syncthreads();
        if (ck + 2 < nchunks)
            issue_stage(sb, ck & 1, (ck + 2) * K_CHUNK, m0, n0, tid);
        cp_commit();
    }

    // ---------------- epilogue: rowdot S * x ----------------
    if (tid < 128) part[tid] = 0.0f;
    __syncthreads();

    #pragma unroll
    for (int mt = 0; mt < 2; ++mt) {
        float ps0 = 0.0f, ps1 = 0.0f;
        #pragma unroll
        for (int nt = 0; nt < 8; ++nt) {
            int col  = n0 + warpN * 64 + nt * 8 + (lane & 3) * 2;
            int rowg = m0 + warpM * 32 + mt * 16 + (lane >> 2);
            float2 x0 = *reinterpret_cast<const float2*>(x + (size_t)rowg * F + col);
            float2 x1 = *reinterpret_cast<const float2*>(x + (size_t)(rowg + 8) * F + col);
            ps0 += acc[mt][nt][0] * x0.x + acc[mt][nt][1] * x0.y;
            ps1 += acc[mt][nt][2] * x1.x + acc[mt][nt][3] * x1.y;
        }
        ps0 += __shfl_xor_sync(0xffffffffu, ps0, 1);
        ps0 += __shfl_xor_sync(0xffffffffu, ps0, 2);
        ps1 += __shfl_xor_sync(0xffffffffu, ps1, 1);
        ps1 += __shfl_xor_sync(0xffffffffu, ps1, 2);
        if ((lane & 3) == 0) {
            int rl = warpM * 32 + mt * 16 + (lane >> 2);
            atomicAdd(&part[rl], ps0);
            atomicAdd(&part[rl + 8], ps1);
        }
    }
    __syncthreads();
    if (tid < 128) atomicAdd(&d_scratch[m0 + tid], part[tid]);
}

// ---------------- launch ----------------
extern "C" void kernel_launch(void* const* d_in, const int* in_sizes, int n_in,
                              void* d_out, int out_size) {
    const float* x = (const float*)d_in[0];     // [16384, 1024] fp32
    const float* w = (const float*)d_in[1];     // [523776] fp32
    float* out = (float*)d_out;                 // [16384] fp32

    convert_x_kernel<<<(BATCHN * F) / (256 * 8), 256>>>(x);
    build_wt_kernel<<<(F * F / 2) / 256, 256>>>(w);
    zero_scratch_kernel<<<BATCHN / 256, 256>>>();

    cudaFuncSetAttribute(poly2_gemm_kernel,
                         cudaFuncAttributeMaxDynamicSharedMemorySize, SMEM_TOTAL);
    dim3 grid(BATCHN / M_TILE, F / N_TILE);     // 128 x 8
    poly2_gemm_kernel<<<grid, NTHREADS, SMEM_TOTAL>>>(x);

    sigmoid_kernel<<<BATCHN / 256, 256>>>(out);
}

// round 7
// speedup vs baseline: 2.4386x; 1.0425x over previous
#include <cuda_runtime.h>
#include <cuda_fp16.h>
#include <cstdint>
#include <math.h>

// POLY2: out_b = sigmoid( sum_{i<j} w_ij * x_bi * x_bj )
// fp16 mma.sync.m16n8k16 + ldmatrix.x4, 3-stage cp.async pipeline (1 sync/chunk),
// triangular K-skip, heavy-tile-first, atomic-free partial reduction.

#define F        1024
#define BATCHN   16384
#define M_TILE   128
#define N_TILE   128
#define K_CHUNK  64
#define NTHREADS 256
#define NBLK     8                    // F / N_TILE
#define STAGES   3

#define ROW_B       144               // padded smem row stride (bytes)
#define TILE_BYTES  (128 * ROW_B)     // 18432 (A or B tile)
#define STAGE_BYTES (2 * TILE_BYTES)  // 36864
#define PART_OFF    (STAGES * STAGE_BYTES)   // 110592
#define SMEM_TOTAL  (PART_OFF + 128 * 4)     // 111104

__device__ __half d_Xh[BATCHN * F];       // X fp16 row-major
__device__ __half d_Wth[F * F];           // Wt[n][k] = w_{k,n} (k<n else 0)
__device__ float  d_part[NBLK * BATCHN];  // per-(n-block) partial z

// ---------------- helpers ----------------
__device__ __forceinline__ uint32_t smem_u32(const void* p) {
    uint32_t a;
    asm("{ .reg .u64 t; cvta.to.shared.u64 t, %1; cvt.u32.u64 %0, t; }" : "=r"(a) : "l"(p));
    return a;
}
__device__ __forceinline__ void cp16(uint32_t dst, const void* src) {
    asm volatile("cp.async.cg.shared.global [%0], [%1], 16;" :: "r"(dst), "l"(src) : "memory");
}
__device__ __forceinline__ void cp_commit() { asm volatile("cp.async.commit_group;" ::: "memory"); }
__device__ __forceinline__ void cp_wait1()  { asm volatile("cp.async.wait_group 1;"  ::: "memory"); }

__device__ __forceinline__ void ldsm4(uint32_t* r, uint32_t addr) {
    asm volatile("ldmatrix.sync.aligned.m8n8.x4.shared.b16 {%0,%1,%2,%3}, [%4];"
        : "=r"(r[0]), "=r"(r[1]), "=r"(r[2]), "=r"(r[3]) : "r"(addr));
}
__device__ __forceinline__ void mma16816(float* c, const uint32_t* a, uint32_t b0, uint32_t b1) {
    asm volatile(
        "mma.sync.aligned.m16n8k16.row.col.f32.f16.f16.f32 "
        "{%0,%1,%2,%3}, {%4,%5,%6,%7}, {%8,%9}, {%0,%1,%2,%3};"
        : "+f"(c[0]), "+f"(c[1]), "+f"(c[2]), "+f"(c[3])
        : "r"(a[0]), "r"(a[1]), "r"(a[2]), "r"(a[3]), "r"(b0), "r"(b1));
}

// ---------------- pre/post kernels ----------------
__global__ void convert_x_kernel(const float* __restrict__ x) {
    int i = (blockIdx.x * 256 + threadIdx.x) * 8;
    float4 v0 = *reinterpret_cast<const float4*>(x + i);
    float4 v1 = *reinterpret_cast<const float4*>(x + i + 4);
    __half2 h[4];
    h[0] = __floats2half2_rn(v0.x, v0.y);
    h[1] = __floats2half2_rn(v0.z, v0.w);
    h[2] = __floats2half2_rn(v1.x, v1.y);
    h[3] = __floats2half2_rn(v1.z, v1.w);
    *reinterpret_cast<uint4*>(d_Xh + i) = *reinterpret_cast<uint4*>(h);
}

__device__ __forceinline__ float w_at(const float* __restrict__ w, int k, int n) {
    if (k >= n) return 0.0f;
    int pi = k * (F - 1) - (k * (k - 1)) / 2 + (n - k - 1);
    return w[pi];
}
__global__ void build_wt_kernel(const float* __restrict__ w) {
    int idx = blockIdx.x * 256 + threadIdx.x;   // over F*F/2 half2 slots
    int n  = idx >> 9;
    int k2 = idx & 511;
    float f0 = w_at(w, 2 * k2,     n);
    float f1 = w_at(w, 2 * k2 + 1, n);
    reinterpret_cast<__half2*>(d_Wth)[idx] = __floats2half2_rn(f0, f1);
}

__global__ void sigmoid_kernel(float* __restrict__ out) {
    int i = blockIdx.x * 256 + threadIdx.x;
    float z = 0.0f;
    #pragma unroll
    for (int j = 0; j < NBLK; ++j) z += d_part[j * BATCHN + i];
    out[i] = 1.0f / (1.0f + __expf(-z));
}

// ---------------- main GEMM + fused rowdot ----------------
extern __shared__ char smem_buf[];

__global__ void __launch_bounds__(NTHREADS, 2)
poly2_gemm_kernel() {
    uint32_t sb = smem_u32(smem_buf);
    float* part = reinterpret_cast<float*>(smem_buf + PART_OFF);

    int tid  = threadIdx.x;
    int lane = tid & 31;
    int wid  = tid >> 5;
    int warpM = wid & 3;                 // 4 warps along M (tile 32)
    int warpN = wid >> 2;                // 2 warps along N (tile 64)
    int m0 = blockIdx.x * M_TILE;
    int by = (int)gridDim.y - 1 - (int)blockIdx.y;   // heavy tiles first
    int n0 = by * N_TILE;

    int nchunks = (n0 + N_TILE) / K_CHUNK;           // 2..16 (triangular skip)

    // --- loader state: one base pointer per operand, +64 halves per stage ---
    int lrow8 = tid >> 3, lcol8 = tid & 7;           // 32 rows x 8 chunks per 256-thread pass
    const __half* agp = d_Xh  + (size_t)(m0 + lrow8) * F + lcol8 * 8;
    const __half* bgp = d_Wth + (size_t)(n0 + lrow8) * F + lcol8 * 8;
    uint32_t sdoff = (uint32_t)(lrow8 * ROW_B + lcol8 * 16);

    #define ISSUE_STAGE(sidx)                                            \
        do {                                                             \
            uint32_t ab = sb + (uint32_t)(sidx) * STAGE_BYTES + sdoff;   \
            _Pragma("unroll")                                            \
            for (int j = 0; j < 4; ++j)                                  \
                cp16(ab + j * (32 * ROW_B), agp + j * (32 * F));         \
            uint32_t bb = ab + TILE_BYTES;                               \
            _Pragma("unroll")                                            \
            for (int j = 0; j < 4; ++j)                                  \
                cp16(bb + j * (32 * ROW_B), bgp + j * (32 * F));         \
            agp += K_CHUNK; bgp += K_CHUNK;                              \
        } while (0)

    float acc[2][8][4];
    #pragma unroll
    for (int mt = 0; mt < 2; ++mt)
        #pragma unroll
        for (int nt = 0; nt < 8; ++nt)
            #pragma unroll
            for (int r = 0; r < 4; ++r) acc[mt][nt][r] = 0.0f;

    // prologue: 2 stages in flight
    ISSUE_STAGE(0); cp_commit();
    ISSUE_STAGE(1); cp_commit();
    cp_wait1();           // stage 0 landed (this thread)
    __syncthreads();      // landed CTA-wide

    // per-lane ldmatrix offsets
    uint32_t lrow  = (uint32_t)(lane & 15);
    uint32_t khalf = (uint32_t)((lane >> 4) * 16);
    uint32_t aoff = (uint32_t)(warpM * 32) * ROW_B + lrow * ROW_B + khalf;
    uint32_t boff = (uint32_t)(warpN * 64) * ROW_B + lrow * ROW_B + khalf + TILE_BYTES;

    int sidx = 2;                                    // next stage buffer to fill
    for (int ck = 0; ck < nchunks; ++ck) {
        // issue stage ck+2 into buffer (ck+2)%3 == (ck-1)%3 (freed by last iter's sync)
        if (ck + 2 < nchunks) {
            ISSUE_STAGE(sidx);
        }
        cp_commit();                                  // uniform group accounting
        if (++sidx == STAGES) sidx = 0;

        uint32_t stbase = sb + (uint32_t)(ck % STAGES) * STAGE_BYTES;
        uint32_t aAddr = stbase + aoff;
        uint32_t bAddr = stbase + boff;

        #pragma unroll
        for (int ks = 0; ks < 4; ++ks) {
            uint32_t a[2][4];
            ldsm4(a[0], aAddr + ks * 32);
            ldsm4(a[1], aAddr + 16 * ROW_B + ks * 32);
            #pragma unroll
            for (int g = 0; g < 4; ++g) {
                uint32_t b[4];
                ldsm4(b, bAddr + (uint32_t)(g * 16) * ROW_B + ks * 32);
                mma16816(acc[0][2 * g],     a[0], b[0], b[2]);
                mma16816(acc[0][2 * g + 1], a[0], b[1], b[3]);
                mma16816(acc[1][2 * g],     a[1], b[0], b[2]);
                mma16816(acc[1][2 * g + 1], a[1], b[1], b[3]);
            }
        }

        cp_wait1();            // stage ck+1 landed (this thread)
        __syncthreads();       // CTA-wide; also: compute on buffer ck%3 done everywhere
    }

    // ---------------- epilogue: rowdot S * x (x from fp16 mirror) ----------------
    if (tid < 128) part[tid] = 0.0f;
    __syncthreads();

    #pragma unroll
    for (int mt = 0; mt < 2; ++mt) {
        float ps0 = 0.0f, ps1 = 0.0f;
        #pragma unroll
        for (int nt = 0; nt < 8; ++nt) {
            int col  = n0 + warpN * 64 + nt * 8 + (lane & 3) * 2;
            int rowg = m0 + warpM * 32 + mt * 16 + (lane >> 2);
            float2 x0 = __half22float2(*reinterpret_cast<const __half2*>(d_Xh + (size_t)rowg * F + col));
            float2 x1 = __half22float2(*reinterpret_cast<const __half2*>(d_Xh + (size_t)(rowg + 8) * F + col));
            ps0 += acc[mt][nt][0] * x0.x + acc[mt][nt][1] * x0.y;
            ps1 += acc[mt][nt][2] * x1.x + acc[mt][nt][3] * x1.y;
        }
        ps0 += __shfl_xor_sync(0xffffffffu, ps0, 1);
        ps0 += __shfl_xor_sync(0xffffffffu, ps0, 2);
        ps1 += __shfl_xor_sync(0xffffffffu, ps1, 1);
        ps1 += __shfl_xor_sync(0xffffffffu, ps1, 2);
        if ((lane & 3) == 0) {
            int rl = warpM * 32 + mt * 16 + (lane >> 2);
            atomicAdd(&part[rl], ps0);          // smem atomics only (cross-warpN merge)
            atomicAdd(&part[rl + 8], ps1);
        }
    }
    __syncthreads();
    if (tid < 128) d_part[by * BATCHN + m0 + tid] = part[tid];   // atomic-free global
}

// ---------------- launch ----------------
extern "C" void kernel_launch(void* const* d_in, const int* in_sizes, int n_in,
                              void* d_out, int out_size) {
    const float* x = (const float*)d_in[0];     // [16384, 1024] fp32
    const float* w = (const float*)d_in[1];     // [523776] fp32
    float* out = (float*)d_out;                 // [16384] fp32

    convert_x_kernel<<<(BATCHN * F) / (256 * 8), 256>>>(x);
    build_wt_kernel<<<(F * F / 2) / 256, 256>>>(w);

    cudaFuncSetAttribute(poly2_gemm_kernel,
                         cudaFuncAttributeMaxDynamicSharedMemorySize, SMEM_TOTAL);
    dim3 grid(BATCHN / M_TILE, NBLK);           // 128 x 8
    poly2_gemm_kernel<<<grid, NTHREADS, SMEM_TOTAL>>>();

    sigmoid_kernel<<<BATCHN / 256, 256>>>(out);
}